// round 14
// baseline (speedup 1.0000x reference)
#include <cuda_runtime.h>
#include <cuda_fp16.h>
#include <math.h>
#include <stdint.h>

#define TOKENS 65536
#define DIN 512
#define HDIM 256
#define BM 64             // tokens per CTA tile
#define KC 32             // fp32 K elements per chunk
#define NCHUNK 16         // 512/32
#define NT 256            // threads per CTA (8 warps: 2M x 4N, warp tile 32x64)
#define ROWB 80           // B smem row bytes (32 fp16 = 64B + 16B pad)
#define AROW 160          // A fp32 smem row bytes (32 fp32 = 128B + 32B pad)
#define GRID 304          // 2 CTAs/SM x 152 SMs, persistent

// ---- dynamic SMEM layout (bytes) ----
#define A_OFF     0       // 3 stages x 10240 (64 rows * 160, raw fp32)
#define A_ST      10240
#define B_OFF     30720   // 3 stages x 20480 (256 rows * 80, fp16)
#define B_STAGE   20480
#define TOK_OFF   92160   // int[2][64]
#define W2_OFF    92672   // float[6*256]
#define B1_OFF    98816   // float[256]
#define B2_OFF    99840   // float[8]
#define RED_OFF   99872   // float[4][64][6]
#define TILE_OFF  106016  // int
#define SMEM_TOTAL 106048

// ---------------- device globals (allocation-free scratch) ----------------
__device__ int g_cnt[3];          // [0]=vcount [1]=pcount [2]=ticket
__device__ int g_vidx[TOKENS];
__device__ int g_pidx[TOKENS];
// prepacked W1 fp16, both heads: [head][chunk 16][256 rows x 64B]
__device__ __align__(16) unsigned char g_wpack[2 * NCHUNK * 16384];

// ---------------- PTX helpers ----------------
__device__ __forceinline__ uint32_t smem_u32(const void* p) {
    uint32_t a;
    asm("{ .reg .u64 t; cvta.to.shared.u64 t, %1; cvt.u32.u64 %0, t; }" : "=r"(a) : "l"(p));
    return a;
}
__device__ __forceinline__ void cp_async16(uint32_t dst, const void* src) {
    asm volatile("cp.async.ca.shared.global [%0], [%1], 16;" :: "r"(dst), "l"(src) : "memory");
}
#define CP_COMMIT() asm volatile("cp.async.commit_group;" ::: "memory")
#define CP_WAIT0()  asm volatile("cp.async.wait_group 0;" ::: "memory")
#define CP_WAIT1()  asm volatile("cp.async.wait_group 1;" ::: "memory")

__device__ __forceinline__ void ldm4(uint32_t (&r)[4], uint32_t addr) {
    asm volatile("ldmatrix.sync.aligned.m8n8.x4.shared.b16 {%0,%1,%2,%3}, [%4];"
        : "=r"(r[0]), "=r"(r[1]), "=r"(r[2]), "=r"(r[3]) : "r"(addr));
}
__device__ __forceinline__ void mma16816(float (&d)[4], const uint32_t (&a)[4],
                                         uint32_t b0, uint32_t b1) {
    asm volatile(
        "mma.sync.aligned.m16n8k16.row.col.f32.f16.f16.f32 "
        "{%0,%1,%2,%3},{%4,%5,%6,%7},{%8,%9},{%0,%1,%2,%3};"
        : "+f"(d[0]), "+f"(d[1]), "+f"(d[2]), "+f"(d[3])
        : "r"(a[0]), "r"(a[1]), "r"(a[2]), "r"(a[3]), "r"(b0), "r"(b1));
}
__device__ __forceinline__ uint32_t packh2(float2 f) {
    uint32_t u;
    asm("cvt.rn.f16x2.f32 %0, %2, %1;" : "=r"(u) : "f"(f.x), "f"(f.y));
    return u;
}

// ---------------- kernel: merged classify + pack ----------------
__global__ void prep_kernel(const int* __restrict__ ids32,
                            const float* __restrict__ vW1, const float* __restrict__ pW1,
                            float* __restrict__ out, int mask_mode) {
    if (blockIdx.x >= 256) {
        int pblk = blockIdx.x - 256;
        int head = pblk >> 7;
        const float* W = head ? pW1 : vW1;
        int q  = (pblk & 127) * 256 + threadIdx.x;   // 0..32767
        int n  = q >> 7;
        int kq = (q & 127) * 4;
        float4 f = *(const float4*)(W + (size_t)n * DIN + kq);
        uint2 hv;
        hv.x = packh2(make_float2(f.x, f.y));
        hv.y = packh2(make_float2(f.z, f.w));
        int chunk = kq >> 5;
        int kk = kq & 31;
        unsigned char* basep = g_wpack + (size_t)head * (NCHUNK * 16384) + (size_t)chunk * 16384;
        *(uint2*)(basep + (size_t)n * 64 + kk * 2) = hv;
        return;
    }

    __shared__ int sIs64;
    if (threadIdx.x < 32) {
        int v = ids32[2 * threadIdx.x + 1] | ids32[2 * threadIdx.x + 65] |
                ids32[2 * threadIdx.x + 129] | ids32[2 * threadIdx.x + 193];
        unsigned nz = __ballot_sync(0xffffffffu, v != 0);
        if (threadIdx.x == 0) sIs64 = (nz == 0);
    }
    __syncthreads();
    int t = blockIdx.x * blockDim.x + threadIdx.x;
    int type = sIs64 ? ids32[2 * t] : ids32[t];
    bool vm = (type == 1);
    bool pm = (type == 2);

    float* row = out + (size_t)t * 6;
    #pragma unroll
    for (int o = 0; o < 6; o++) row[o] = 0.0f;

    if (mask_mode == 1) {
        out[TOKENS * 6 + t]          = vm ? 1.0f : 0.0f;
        out[TOKENS * 6 + TOKENS + t] = pm ? 1.0f : 0.0f;
    } else if (mask_mode == 2) {
        unsigned char* m = (unsigned char*)(out + TOKENS * 6);
        m[t]          = vm ? 1 : 0;
        m[TOKENS + t] = pm ? 1 : 0;
    }

    int lane = threadIdx.x & 31;
    unsigned vb = __ballot_sync(0xffffffffu, vm);
    if (vm) {
        int leader = __ffs(vb) - 1;
        int base = 0;
        if (lane == leader) base = atomicAdd(&g_cnt[0], __popc(vb));
        base = __shfl_sync(vb, base, leader);
        g_vidx[base + __popc(vb & ((1u << lane) - 1u))] = t;
    }
    unsigned pb = __ballot_sync(0xffffffffu, pm);
    if (pm) {
        int leader = __ffs(pb) - 1;
        int base = 0;
        if (lane == leader) base = atomicAdd(&g_cnt[1], __popc(pb));
        base = __shfl_sync(pb, base, leader);
        g_pidx[base + __popc(pb & ((1u << lane) - 1u))] = t;
    }
}

// ---------------- kernel: persistent fp16 HMMA MLP (3-stage cp.async pipeline) ----------------
__global__ __launch_bounds__(NT, 2)
void mlp_kernel(const float* __restrict__ repr3,
                const float* __restrict__ vW2, const float* __restrict__ vB1, const float* __restrict__ vB2,
                const float* __restrict__ pW2, const float* __restrict__ pB1, const float* __restrict__ pB2,
                float* __restrict__ out)
{
    extern __shared__ unsigned char smem[];
    const uint32_t sb = smem_u32(smem);
    const int tid  = threadIdx.x;
    const int wid  = tid >> 5;
    const int lane = tid & 31;
    const int wm = wid & 1;          // 2 M halves of 32 rows
    const int wn = wid >> 1;         // 4 N quarters of 64 cols
    const int m0 = wm * 32;
    const int n0 = wn * 64;
    const int afr = lane >> 2;       // a-frag row within 8-group
    const int afk = (lane & 3) * 2;  // a-frag k pair base

    int*   tok   = (int*)(smem + TOK_OFF);       // [2][64]
    float* sW2   = (float*)(smem + W2_OFF);
    float* sB1   = (float*)(smem + B1_OFF);
    float* sB2   = (float*)(smem + B2_OFF);
    float* sRed  = (float*)(smem + RED_OFF);
    int*   sTile = (int*)(smem + TILE_OFF);

    const int nv = g_cnt[0], np = g_cnt[1];
    const int nvt = (nv + BM - 1) / BM;
    const int npt = (np + BM - 1) / BM;
    const int ntiles = nvt + npt;

    const uint32_t bLdOff = (uint32_t)(((lane >> 4) & 1) * 8 + (lane & 7)) * ROWB
                          + (uint32_t)((lane >> 3) & 1) * 16;

    auto issueA = [&](const int* tokp, int ch, uint32_t dstBase) {
        #pragma unroll
        for (int i = 0; i < 2; i++) {
            int idx = tid + i * NT;          // 0..511
            int row = idx >> 3;
            int c16 = idx & 7;
            const float* src = repr3 + (size_t)tokp[row] * DIN + ch * KC + c16 * 4;
            cp_async16(dstBase + (uint32_t)row * AROW + c16 * 16, src);
        }
    };
    auto issueB = [&](const unsigned char* wsrc, int ch, uint32_t dstBase) {
        const unsigned char* csrc = wsrc + (size_t)ch * 16384;
        #pragma unroll
        for (int i = 0; i < 4; i++) {
            int idx = tid + i * NT;          // 0..1023
            int row = idx >> 2;
            int c16 = idx & 3;
            cp_async16(dstBase + (uint32_t)row * ROWB + c16 * 16,
                       csrc + (size_t)row * 64 + c16 * 16);
        }
    };

    // ---- first ticket + token list + chunks 0,1 in flight ----
    if (tid == 0) *sTile = atomicAdd(&g_cnt[2], 1);
    __syncthreads();
    int tile = *sTile;
    int par = 0;
    if (tile < ntiles) {
        int h = (tile >= nvt);
        int tIdx = h ? (tile - nvt) : tile;
        int cnt  = h ? np : nv;
        const int* list = h ? g_pidx : g_vidx;
        if (tid < BM) {
            int m = tIdx * BM + tid;
            tok[tid] = (m < cnt) ? list[m] : list[0];
        }
    }
    __syncthreads();
    if (tile < ntiles) {
        int h = (tile >= nvt);
        const unsigned char* ws = g_wpack + (size_t)h * (NCHUNK * 16384);
        issueB(ws, 0, sb + B_OFF);           issueA(tok, 0, sb + A_OFF);           CP_COMMIT();
        issueB(ws, 1, sb + B_OFF + B_STAGE); issueA(tok, 1, sb + A_OFF + A_ST);    CP_COMMIT();
    }

    int prevHead = -1;

    while (tile < ntiles) {
        const int head  = (tile >= nvt);
        const int tIdx  = head ? (tile - nvt) : tile;
        const int count = head ? np : nv;
        const int base  = tIdx * BM;
        const int odim  = head ? 2 : 6;
        const unsigned char* wsrc = g_wpack + (size_t)head * (NCHUNK * 16384);
        const int* tokp = tok + par * BM;

        if (head != prevHead) {
            const float* W2p = head ? pW2 : vW2;
            const float* B1p = head ? pB1 : vB1;
            const float* B2p = head ? pB2 : vB2;
            for (int i = tid; i < 6 * HDIM; i += NT) sW2[i] = (i < odim * HDIM) ? W2p[i] : 0.0f;
            for (int i = tid; i < HDIM; i += NT) sB1[i] = B1p[i];
            if (tid < odim) sB2[tid] = B2p[tid];
            prevHead = head;
            __syncthreads();
        }

        float c[2][8][4];
        #pragma unroll
        for (int mi = 0; mi < 2; mi++)
            #pragma unroll
            for (int ni = 0; ni < 8; ni++)
                #pragma unroll
                for (int j = 0; j < 4; j++) c[mi][ni][j] = 0.0f;

        auto compute = [&](int s) {
            const unsigned char* aP = smem + A_OFF + s * A_ST;
            const uint32_t bB = sb + B_OFF + s * B_STAGE;
            #pragma unroll
            for (int ks = 0; ks < 2; ks++) {
                const int kb = ks * 16;
                uint32_t ah[2][4];
                #pragma unroll
                for (int mi = 0; mi < 2; mi++) {
                    const unsigned char* rp = aP + (uint32_t)(m0 + mi * 16 + afr) * AROW
                                            + (uint32_t)(kb + afk) * 4;
                    ah[mi][0] = packh2(*(const float2*)(rp));
                    ah[mi][1] = packh2(*(const float2*)(rp + 8 * AROW));
                    ah[mi][2] = packh2(*(const float2*)(rp + 32));
                    ah[mi][3] = packh2(*(const float2*)(rp + 8 * AROW + 32));
                }
                #pragma unroll
                for (int npp = 0; npp < 4; npp++) {
                    uint32_t b[4];
                    ldm4(b, bB + (uint32_t)(n0 + npp * 16) * ROWB + (uint32_t)ks * 32 + bLdOff);
                    mma16816(c[0][2 * npp],     ah[0], b[0], b[1]);
                    mma16816(c[0][2 * npp + 1], ah[0], b[2], b[3]);
                    mma16816(c[1][2 * npp],     ah[1], b[0], b[1]);
                    mma16816(c[1][2 * npp + 1], ah[1], b[2], b[3]);
                }
            }
        };

        // ---- main K loop: wait(1) -> barrier -> issue ch+2 -> compute ch ----
        int s = 0, s2 = 2;   // s = ch%3, s2 = (ch+2)%3
        for (int ch = 0; ch < NCHUNK - 1; ch++) {
            CP_WAIT1();
            __syncthreads();
            if (ch + 2 < NCHUNK) {
                issueB(wsrc, ch + 2, sb + B_OFF + s2 * B_STAGE);
                issueA(tokp, ch + 2, sb + A_OFF + s2 * A_ST);
                CP_COMMIT();
            }
            compute(s);
            s = (s == 2) ? 0 : s + 1;
            s2 = (s2 == 2) ? 0 : s2 + 1;
        }
        // last chunk
        CP_WAIT0();
        __syncthreads();
        compute(s);

        // ---- next ticket + token list + its chunks 0,1 (pipe refill under epilogue) ----
        if (tid == 0) *sTile = atomicAdd(&g_cnt[2], 1);
        __syncthreads();          // also retires all readers of stages 0..2
        const int ntile = *sTile;
        const int npar = par ^ 1;
        if (ntile < ntiles) {
            int nh = (ntile >= nvt);
            int ntIdx = nh ? (ntile - nvt) : ntile;
            int ncnt  = nh ? np : nv;
            const int* nlist = nh ? g_pidx : g_vidx;
            if (tid < BM) {
                int m = ntIdx * BM + tid;
                tok[npar * BM + tid] = (m < ncnt) ? nlist[m] : nlist[0];
            }
        }
        __syncthreads();
        if (ntile < ntiles) {
            int nh = (ntile >= nvt);
            const unsigned char* nws = g_wpack + (size_t)nh * (NCHUNK * 16384);
            issueB(nws, 0, sb + B_OFF);           issueA(tok + npar * BM, 0, sb + A_OFF);        CP_COMMIT();
            issueB(nws, 1, sb + B_OFF + B_STAGE); issueA(tok + npar * BM, 1, sb + A_OFF + A_ST); CP_COMMIT();
        }

        // ---- epilogue: bias + exact GELU + 256->{6,2} layer ----
        #pragma unroll
        for (int mi = 0; mi < 2; mi++) {
            #pragma unroll
            for (int half = 0; half < 2; half++) {
                float a6[6] = {0.f, 0.f, 0.f, 0.f, 0.f, 0.f};
                #pragma unroll
                for (int ni = 0; ni < 8; ni++) {
                    #pragma unroll
                    for (int e = 0; e < 2; e++) {
                        int col = n0 + ni * 8 + (lane & 3) * 2 + e;
                        float x = c[mi][ni][half * 2 + e] + sB1[col];
                        float hgl = 0.5f * x * (1.0f + erff(x * 0.70710678118654752f));
                        a6[0] = fmaf(hgl, sW2[0 * HDIM + col], a6[0]);
                        a6[1] = fmaf(hgl, sW2[1 * HDIM + col], a6[1]);
                        if (odim == 6) {
                            a6[2] = fmaf(hgl, sW2[2 * HDIM + col], a6[2]);
                            a6[3] = fmaf(hgl, sW2[3 * HDIM + col], a6[3]);
                            a6[4] = fmaf(hgl, sW2[4 * HDIM + col], a6[4]);
                            a6[5] = fmaf(hgl, sW2[5 * HDIM + col], a6[5]);
                        }
                    }
                }
                #pragma unroll
                for (int o = 0; o < 6; o++) {
                    a6[o] += __shfl_xor_sync(0xffffffffu, a6[o], 1);
                    a6[o] += __shfl_xor_sync(0xffffffffu, a6[o], 2);
                }
                if ((lane & 3) == 0) {
                    int row = m0 + mi * 16 + half * 8 + (lane >> 2);
                    #pragma unroll
                    for (int o = 0; o < 6; o++)
                        sRed[(wn * BM + row) * 6 + o] = a6[o];
                }
            }
        }
        __syncthreads();

        if (tid < BM && base + tid < count) {
            float* orow = out + (size_t)tokp[tid] * 6;
            #pragma unroll
            for (int o = 0; o < 6; o++) {
                if (o < odim) {
                    float v = sRed[(0 * BM + tid) * 6 + o] + sRed[(1 * BM + tid) * 6 + o]
                            + sRed[(2 * BM + tid) * 6 + o] + sRed[(3 * BM + tid) * 6 + o]
                            + sB2[o];
                    orow[o] = v;
                }
            }
        }
        __syncthreads();   // sRed/tok consumed before next tile
        tile = ntile;
        par = npar;
    }
}

// ---------------- launch ----------------
extern "C" void kernel_launch(void* const* d_in, const int* in_sizes, int n_in,
                              void* d_out, int out_size) {
    const float* repr3 = (const float*)d_in[0];
    const int*   ids   = (const int*)d_in[1];
    const float* vW1 = (const float*)d_in[2];
    const float* vb1 = (const float*)d_in[3];
    const float* vW2 = (const float*)d_in[4];
    const float* vb2 = (const float*)d_in[5];
    const float* pW1 = (const float*)d_in[6];
    const float* pb1 = (const float*)d_in[7];
    const float* pW2 = (const float*)d_in[8];
    const float* pb2 = (const float*)d_in[9];
    float* out = (float*)d_out;

    int mask_mode = 0;
    if (out_size >= TOKENS * 6 + 2 * TOKENS)      mask_mode = 1;
    else if (out_size >= TOKENS * 6 + TOKENS / 2) mask_mode = 2;

    cudaFuncSetAttribute(mlp_kernel, cudaFuncAttributeMaxDynamicSharedMemorySize, SMEM_TOTAL);

    void* cntAddr = nullptr;
    cudaGetSymbolAddress(&cntAddr, g_cnt);
    cudaMemsetAsync(cntAddr, 0, 3 * sizeof(int));

    prep_kernel<<<512, 256>>>(ids, vW1, pW1, out, mask_mode);
    mlp_kernel<<<GRID, NT, SMEM_TOTAL>>>(repr3, vW2, vb1, vb2, pW2, pb1, pb2, out);
}

// round 15
// speedup vs baseline: 1.0871x; 1.0871x over previous
#include <cuda_runtime.h>
#include <cuda_fp16.h>
#include <math.h>
#include <stdint.h>

#define TOKENS 65536
#define DIN 512
#define HDIM 256
#define BM 64             // tokens per CTA tile
#define KC 32             // fp32 K elements per chunk
#define NCHUNK 16         // 512/32
#define NT 256            // threads per CTA (8 warps: 2M x 4N, warp tile 32x64)
#define ROWB 80           // A16/B smem row bytes (32 fp16 = 64B + 16B pad)
#define AROW32 160        // A32 smem row bytes (32 fp32 = 128B + 32B pad)
#define GRID 304          // 2 CTAs/SM x 152 SMs, persistent

// ---- dynamic SMEM layout (bytes) ----
#define A32_OFF   0       // 3 stages x 10240 (64 rows * 160, raw fp32)
#define A32_ST    10240
#define A16_OFF   30720   // 2 stages x 5120 (64 rows * 80, fp16)
#define A16_ST    5120
#define B_OFF     40960   // 2 stages x 20480 (256 rows * 80, fp16)
#define B_STAGE   20480
#define TOK_OFF   81920   // int[2][64]
#define W2_OFF    82432   // float[6*256]
#define B1_OFF    88576   // float[256]
#define B2_OFF    89600   // float[8]
#define RED_OFF   89632   // float[4][64][6]
#define TILE_OFF  95776   // int
#define SMEM_TOTAL 95808

// ---------------- device globals (allocation-free scratch) ----------------
__device__ int g_cnt[3];          // [0]=vcount [1]=pcount [2]=ticket
__device__ int g_vidx[TOKENS];
__device__ int g_pidx[TOKENS];
// prepacked W1 fp16, both heads: [head][chunk 16][256 rows x 64B]
__device__ __align__(16) unsigned char g_wpack[2 * NCHUNK * 16384];

// ---------------- PTX helpers ----------------
__device__ __forceinline__ uint32_t smem_u32(const void* p) {
    uint32_t a;
    asm("{ .reg .u64 t; cvta.to.shared.u64 t, %1; cvt.u32.u64 %0, t; }" : "=r"(a) : "l"(p));
    return a;
}
__device__ __forceinline__ void cp_async16(uint32_t dst, const void* src) {
    asm volatile("cp.async.ca.shared.global [%0], [%1], 16;" :: "r"(dst), "l"(src) : "memory");
}
#define CP_COMMIT() asm volatile("cp.async.commit_group;" ::: "memory")
#define CP_WAIT0()  asm volatile("cp.async.wait_group 0;" ::: "memory")
#define CP_WAIT1()  asm volatile("cp.async.wait_group 1;" ::: "memory")

__device__ __forceinline__ void ldm4(uint32_t (&r)[4], uint32_t addr) {
    asm volatile("ldmatrix.sync.aligned.m8n8.x4.shared.b16 {%0,%1,%2,%3}, [%4];"
        : "=r"(r[0]), "=r"(r[1]), "=r"(r[2]), "=r"(r[3]) : "r"(addr));
}
__device__ __forceinline__ void mma16816(float (&d)[4], const uint32_t (&a)[4],
                                         uint32_t b0, uint32_t b1) {
    asm volatile(
        "mma.sync.aligned.m16n8k16.row.col.f32.f16.f16.f32 "
        "{%0,%1,%2,%3},{%4,%5,%6,%7},{%8,%9},{%0,%1,%2,%3};"
        : "+f"(d[0]), "+f"(d[1]), "+f"(d[2]), "+f"(d[3])
        : "r"(a[0]), "r"(a[1]), "r"(a[2]), "r"(a[3]), "r"(b0), "r"(b1));
}
__device__ __forceinline__ uint32_t packh2(float2 f) {
    uint32_t u;
    asm("cvt.rn.f16x2.f32 %0, %2, %1;" : "=r"(u) : "f"(f.x), "f"(f.y));
    return u;
}

// ---------------- kernel: merged classify + pack ----------------
__global__ void prep_kernel(const int* __restrict__ ids32,
                            const float* __restrict__ vW1, const float* __restrict__ pW1,
                            float* __restrict__ out, int mask_mode) {
    if (blockIdx.x >= 256) {
        int pblk = blockIdx.x - 256;
        int head = pblk >> 7;
        const float* W = head ? pW1 : vW1;
        int q  = (pblk & 127) * 256 + threadIdx.x;   // 0..32767
        int n  = q >> 7;
        int kq = (q & 127) * 4;
        float4 f = *(const float4*)(W + (size_t)n * DIN + kq);
        uint2 hv;
        hv.x = packh2(make_float2(f.x, f.y));
        hv.y = packh2(make_float2(f.z, f.w));
        int chunk = kq >> 5;
        int kk = kq & 31;
        unsigned char* basep = g_wpack + (size_t)head * (NCHUNK * 16384) + (size_t)chunk * 16384;
        *(uint2*)(basep + (size_t)n * 64 + kk * 2) = hv;
        return;
    }

    __shared__ int sIs64;
    if (threadIdx.x < 32) {
        int v = ids32[2 * threadIdx.x + 1] | ids32[2 * threadIdx.x + 65] |
                ids32[2 * threadIdx.x + 129] | ids32[2 * threadIdx.x + 193];
        unsigned nz = __ballot_sync(0xffffffffu, v != 0);
        if (threadIdx.x == 0) sIs64 = (nz == 0);
    }
    __syncthreads();
    int t = blockIdx.x * blockDim.x + threadIdx.x;
    int type = sIs64 ? ids32[2 * t] : ids32[t];
    bool vm = (type == 1);
    bool pm = (type == 2);

    float* row = out + (size_t)t * 6;
    #pragma unroll
    for (int o = 0; o < 6; o++) row[o] = 0.0f;

    if (mask_mode == 1) {
        out[TOKENS * 6 + t]          = vm ? 1.0f : 0.0f;
        out[TOKENS * 6 + TOKENS + t] = pm ? 1.0f : 0.0f;
    } else if (mask_mode == 2) {
        unsigned char* m = (unsigned char*)(out + TOKENS * 6);
        m[t]          = vm ? 1 : 0;
        m[TOKENS + t] = pm ? 1 : 0;
    }

    int lane = threadIdx.x & 31;
    unsigned vb = __ballot_sync(0xffffffffu, vm);
    if (vm) {
        int leader = __ffs(vb) - 1;
        int base = 0;
        if (lane == leader) base = atomicAdd(&g_cnt[0], __popc(vb));
        base = __shfl_sync(vb, base, leader);
        g_vidx[base + __popc(vb & ((1u << lane) - 1u))] = t;
    }
    unsigned pb = __ballot_sync(0xffffffffu, pm);
    if (pm) {
        int leader = __ffs(pb) - 1;
        int base = 0;
        if (lane == leader) base = atomicAdd(&g_cnt[1], __popc(pb));
        base = __shfl_sync(pb, base, leader);
        g_pidx[base + __popc(pb & ((1u << lane) - 1u))] = t;
    }
}

// ---------------- kernel: persistent fp16 HMMA MLP (A 3-deep cp.async + smem convert) ----------------
__global__ __launch_bounds__(NT, 2)
void mlp_kernel(const float* __restrict__ repr3,
                const float* __restrict__ vW2, const float* __restrict__ vB1, const float* __restrict__ vB2,
                const float* __restrict__ pW2, const float* __restrict__ pB1, const float* __restrict__ pB2,
                float* __restrict__ out)
{
    extern __shared__ unsigned char smem[];
    const uint32_t sb = smem_u32(smem);
    const int tid  = threadIdx.x;
    const int wid  = tid >> 5;
    const int lane = tid & 31;
    const int wm = wid & 1;          // 2 M tiles of 32 rows
    const int wn = wid >> 1;         // 4 N tiles of 64 cols
    const int m0 = wm * 32;
    const int n0 = wn * 64;

    int*   tok   = (int*)(smem + TOK_OFF);       // [2][64]
    float* sW2   = (float*)(smem + W2_OFF);
    float* sB1   = (float*)(smem + B1_OFF);
    float* sB2   = (float*)(smem + B2_OFF);
    float* sRed  = (float*)(smem + RED_OFF);
    int*   sTile = (int*)(smem + TILE_OFF);

    const int nv = g_cnt[0], np = g_cnt[1];
    const int nvt = (nv + BM - 1) / BM;
    const int npt = (np + BM - 1) / BM;
    const int ntiles = nvt + npt;

    const uint32_t aLdOff = (uint32_t)(((lane >> 3) & 1) * 8 + (lane & 7)) * ROWB + (uint32_t)(lane >> 4) * 16;
    const uint32_t bLdOff = (uint32_t)(((lane >> 4) & 1) * 8 + (lane & 7)) * ROWB + (uint32_t)((lane >> 3) & 1) * 16;

    // A32: 512 float4 per chunk; 2 cp.async per thread
    auto issueA32 = [&](const int* tokp, int ch) {
        uint32_t dstBase = sb + A32_OFF + (uint32_t)(ch % 3) * A32_ST;
        #pragma unroll
        for (int i = 0; i < 2; i++) {
            int idx = tid + i * NT;          // 0..511
            int row = idx >> 3;
            int c16 = idx & 7;
            cp_async16(dstBase + (uint32_t)row * AROW32 + c16 * 16,
                       repr3 + (size_t)tokp[row] * DIN + ch * KC + c16 * 4);
        }
    };
    // B: 1024 x 16B per chunk; 4 cp.async per thread
    auto issueB = [&](const unsigned char* wsrc, int ch) {
        const unsigned char* csrc = wsrc + (size_t)ch * 16384;
        uint32_t dstBase = sb + B_OFF + (uint32_t)(ch & 1) * B_STAGE;
        #pragma unroll
        for (int i = 0; i < 4; i++) {
            int idx = tid + i * NT;          // 0..1023
            int row = idx >> 2;
            int c16 = idx & 3;
            cp_async16(dstBase + (uint32_t)row * ROWB + c16 * 16,
                       csrc + (size_t)row * 64 + c16 * 16);
        }
    };
    // bulk convert A32 stage (ch%3) -> A16 stage (ch&1); 8 floats per thread
    auto convertA = [&](int ch) {
        const unsigned char* src = smem + A32_OFF + (ch % 3) * A32_ST;
        unsigned char* dst = smem + A16_OFF + (ch & 1) * A16_ST;
        #pragma unroll
        for (int i = 0; i < 2; i++) {
            int idx = tid + i * NT;
            int row = idx >> 3;
            int c16 = idx & 7;
            float4 f = *(const float4*)(src + (uint32_t)row * AROW32 + c16 * 16);
            uint2 hv;
            hv.x = packh2(make_float2(f.x, f.y));
            hv.y = packh2(make_float2(f.z, f.w));
            *(uint2*)(dst + (uint32_t)row * ROWB + c16 * 8) = hv;
        }
    };
    // fill groups for a tile: A32(0) | A32(1) | B(0) | A32(2), one commit each
    auto issueFill = [&](const int* tokp, const unsigned char* wsrc) {
        issueA32(tokp, 0); CP_COMMIT();
        issueA32(tokp, 1); CP_COMMIT();
        issueB(wsrc, 0);   CP_COMMIT();
        issueA32(tokp, 2); CP_COMMIT();
    };

    // ---- first ticket + token list + fill ----
    if (tid == 0) *sTile = atomicAdd(&g_cnt[2], 1);
    __syncthreads();
    int tile = *sTile;
    int par = 0;
    if (tile < ntiles) {
        int h = (tile >= nvt);
        int tIdx = h ? (tile - nvt) : tile;
        int cnt  = h ? np : nv;
        const int* list = h ? g_pidx : g_vidx;
        if (tid < BM) {
            int m = tIdx * BM + tid;
            tok[tid] = (m < cnt) ? list[m] : list[0];
        }
    }
    __syncthreads();
    if (tile < ntiles)
        issueFill(tok, g_wpack + (size_t)(tile >= nvt) * (NCHUNK * 16384));

    int prevHead = -1;

    while (tile < ntiles) {
        const int head  = (tile >= nvt);
        const int tIdx  = head ? (tile - nvt) : tile;
        const int count = head ? np : nv;
        const int base  = tIdx * BM;
        const int odim  = head ? 2 : 6;
        const unsigned char* wsrc = g_wpack + (size_t)head * (NCHUNK * 16384);
        const int* tokp = tok + par * BM;

        if (head != prevHead) {
            const float* W2p = head ? pW2 : vW2;
            const float* B1p = head ? pB1 : vB1;
            const float* B2p = head ? pB2 : vB2;
            for (int i = tid; i < 6 * HDIM; i += NT) sW2[i] = (i < odim * HDIM) ? W2p[i] : 0.0f;
            if (tid < HDIM) sB1[tid] = B1p[tid];
            if (tid < odim) sB2[tid] = B2p[tid];
            prevHead = head;
        }

        float c[2][8][4];
        #pragma unroll
        for (int mi = 0; mi < 2; mi++)
            #pragma unroll
            for (int ni = 0; ni < 8; ni++)
                #pragma unroll
                for (int j = 0; j < 4; j++) c[mi][ni][j] = 0.0f;

        // ---- fill wait: A32(0,1), B(0) done; A32(2) may fly ----
        CP_WAIT1();
        __syncthreads();
        convertA(0);

        // ---- main K loop ----
        for (int ch = 0; ch < NCHUNK; ch++) {
            if (ch >= NCHUNK - 3) { CP_WAIT0(); } else { CP_WAIT1(); }
            __syncthreads();
            if (ch + 1 < NCHUNK) { issueB(wsrc, ch + 1); CP_COMMIT(); }
            if (ch + 3 < NCHUNK) { issueA32(tokp, ch + 3); CP_COMMIT(); }
            if (ch + 1 < NCHUNK) convertA(ch + 1);

            const uint32_t aB = sb + A16_OFF + (uint32_t)(ch & 1) * A16_ST;
            const uint32_t bB = sb + B_OFF + (uint32_t)(ch & 1) * B_STAGE;
            #pragma unroll
            for (int ks = 0; ks < 2; ks++) {
                uint32_t ah[2][4];
                #pragma unroll
                for (int mi = 0; mi < 2; mi++) {
                    uint32_t off = (uint32_t)(m0 + mi * 16) * ROWB + (uint32_t)ks * 32 + aLdOff;
                    ldm4(ah[mi], aB + off);
                }
                #pragma unroll
                for (int npp = 0; npp < 4; npp++) {
                    uint32_t off = (uint32_t)(n0 + npp * 16) * ROWB + (uint32_t)ks * 32 + bLdOff;
                    uint32_t b[4];
                    ldm4(b, bB + off);
                    mma16816(c[0][2 * npp],     ah[0], b[0], b[1]);
                    mma16816(c[0][2 * npp + 1], ah[0], b[2], b[3]);
                    mma16816(c[1][2 * npp],     ah[1], b[0], b[1]);
                    mma16816(c[1][2 * npp + 1], ah[1], b[2], b[3]);
                }
            }
        }

        // ---- next ticket + token list + next-tile fill (flies under epilogue) ----
        if (tid == 0) *sTile = atomicAdd(&g_cnt[2], 1);
        __syncthreads();          // all compute done; pipe fully drained (last 3 windows waited 0)
        const int ntile = *sTile;
        const int npar = par ^ 1;
        if (ntile < ntiles) {
            int nh = (ntile >= nvt);
            int ntIdx = nh ? (ntile - nvt) : ntile;
            int ncnt  = nh ? np : nv;
            const int* nlist = nh ? g_pidx : g_vidx;
            if (tid < BM) {
                int m = ntIdx * BM + tid;
                tok[npar * BM + tid] = (m < ncnt) ? nlist[m] : nlist[0];
            }
        }
        __syncthreads();
        if (ntile < ntiles)
            issueFill(tok + npar * BM, g_wpack + (size_t)(ntile >= nvt) * (NCHUNK * 16384));

        // ---- epilogue: bias + exact GELU + 256->{6,2} layer ----
        if (odim == 6) {
            #pragma unroll
            for (int mi = 0; mi < 2; mi++) {
                #pragma unroll
                for (int half = 0; half < 2; half++) {
                    float a6[6] = {0.f, 0.f, 0.f, 0.f, 0.f, 0.f};
                    #pragma unroll
                    for (int ni = 0; ni < 8; ni++) {
                        #pragma unroll
                        for (int e = 0; e < 2; e++) {
                            int col = n0 + ni * 8 + (lane & 3) * 2 + e;
                            float x = c[mi][ni][half * 2 + e] + sB1[col];
                            float hgl = 0.5f * x * (1.0f + erff(x * 0.70710678118654752f));
                            #pragma unroll
                            for (int o = 0; o < 6; o++)
                                a6[o] = fmaf(hgl, sW2[o * HDIM + col], a6[o]);
                        }
                    }
                    #pragma unroll
                    for (int o = 0; o < 6; o++) {
                        a6[o] += __shfl_xor_sync(0xffffffffu, a6[o], 1);
                        a6[o] += __shfl_xor_sync(0xffffffffu, a6[o], 2);
                    }
                    if ((lane & 3) == 0) {
                        int row = m0 + mi * 16 + half * 8 + (lane >> 2);
                        #pragma unroll
                        for (int o = 0; o < 6; o++)
                            sRed[(wn * BM + row) * 6 + o] = a6[o];
                    }
                }
            }
        } else {
            #pragma unroll
            for (int mi = 0; mi < 2; mi++) {
                #pragma unroll
                for (int half = 0; half < 2; half++) {
                    float a2[2] = {0.f, 0.f};
                    #pragma unroll
                    for (int ni = 0; ni < 8; ni++) {
                        #pragma unroll
                        for (int e = 0; e < 2; e++) {
                            int col = n0 + ni * 8 + (lane & 3) * 2 + e;
                            float x = c[mi][ni][half * 2 + e] + sB1[col];
                            float hgl = 0.5f * x * (1.0f + erff(x * 0.70710678118654752f));
                            a2[0] = fmaf(hgl, sW2[0 * HDIM + col], a2[0]);
                            a2[1] = fmaf(hgl, sW2[1 * HDIM + col], a2[1]);
                        }
                    }
                    #pragma unroll
                    for (int o = 0; o < 2; o++) {
                        a2[o] += __shfl_xor_sync(0xffffffffu, a2[o], 1);
                        a2[o] += __shfl_xor_sync(0xffffffffu, a2[o], 2);
                    }
                    if ((lane & 3) == 0) {
                        int row = m0 + mi * 16 + half * 8 + (lane >> 2);
                        sRed[(wn * BM + row) * 6 + 0] = a2[0];
                        sRed[(wn * BM + row) * 6 + 1] = a2[1];
                    }
                }
            }
        }
        __syncthreads();

        if (tid < BM && base + tid < count) {
            float* orow = out + (size_t)tokp[tid] * 6;
            #pragma unroll
            for (int o = 0; o < 6; o++) {
                if (o < odim) {
                    float v = sRed[(0 * BM + tid) * 6 + o] + sRed[(1 * BM + tid) * 6 + o]
                            + sRed[(2 * BM + tid) * 6 + o] + sRed[(3 * BM + tid) * 6 + o]
                            + sB2[o];
                    orow[o] = v;
                }
            }
        }
        __syncthreads();   // sRed/tok consumed before next tile
        tile = ntile;
        par = npar;
    }
}

// ---------------- launch ----------------
extern "C" void kernel_launch(void* const* d_in, const int* in_sizes, int n_in,
                              void* d_out, int out_size) {
    const float* repr3 = (const float*)d_in[0];
    const int*   ids   = (const int*)d_in[1];
    const float* vW1 = (const float*)d_in[2];
    const float* vb1 = (const float*)d_in[3];
    const float* vW2 = (const float*)d_in[4];
    const float* vb2 = (const float*)d_in[5];
    const float* pW1 = (const float*)d_in[6];
    const float* pb1 = (const float*)d_in[7];
    const float* pW2 = (const float*)d_in[8];
    const float* pb2 = (const float*)d_in[9];
    float* out = (float*)d_out;

    int mask_mode = 0;
    if (out_size >= TOKENS * 6 + 2 * TOKENS)      mask_mode = 1;
    else if (out_size >= TOKENS * 6 + TOKENS / 2) mask_mode = 2;

    cudaFuncSetAttribute(mlp_kernel, cudaFuncAttributeMaxDynamicSharedMemorySize, SMEM_TOTAL);

    void* cntAddr = nullptr;
    cudaGetSymbolAddress(&cntAddr, g_cnt);
    cudaMemsetAsync(cntAddr, 0, 3 * sizeof(int));

    prep_kernel<<<512, 256>>>(ids, vW1, pW1, out, mask_mode);
    mlp_kernel<<<GRID, NT, SMEM_TOTAL>>>(repr3, vW2, vb1, vb2, pW2, pb1, pb2, out);
}

// round 16
// speedup vs baseline: 1.1445x; 1.0528x over previous
#include <cuda_runtime.h>
#include <cuda_fp16.h>
#include <math.h>
#include <stdint.h>

#define TOKENS 65536
#define DIN 512
#define HDIM 256
#define BM 64             // tokens per CTA tile
#define KC 32             // fp32 K elements per chunk
#define NCHUNK 16         // 512/32
#define NSTAGE 4          // ring depth
#define NT 384            // 8 consumer warps + 4 producer warps
#define NPROD 128         // producer threads
#define ROWB 80           // fp16 smem row bytes (64B + 16B pad)
#define GRID 152          // 1 CTA/SM, persistent

// ---- dynamic SMEM layout (bytes) ----
#define A16_OFF   0       // 4 stages x 5120 (64 rows * 80)
#define A16_ST    5120
#define B_OFF     20480   // 4 stages x 20480 (256 rows * 80)
#define B_ST      20480
#define TOK_OFF   102400  // int[64]
#define W2_OFF    102656  // float[6*256]
#define B1_OFF    108800  // float[256]
#define B2_OFF    109824  // float[8]
#define RED_OFF   109856  // float[4][64][6]
#define MBAR_OFF  116000  // 4 x (full,empty) u64 pairs
#define TILE_OFF  116064  // int
#define SMEM_TOTAL 116096

// ---------------- device globals ----------------
__device__ int g_cnt[3];          // [0]=vcount [1]=pcount [2]=ticket
__device__ int g_vidx[TOKENS];
__device__ int g_pidx[TOKENS];
__device__ __align__(16) unsigned char g_wpack[2 * NCHUNK * 16384];

// ---------------- PTX helpers ----------------
__device__ __forceinline__ uint32_t smem_u32(const void* p) {
    uint32_t a;
    asm("{ .reg .u64 t; cvta.to.shared.u64 t, %1; cvt.u32.u64 %0, t; }" : "=r"(a) : "l"(p));
    return a;
}
__device__ __forceinline__ void cp_async16(uint32_t dst, const void* src) {
    asm volatile("cp.async.ca.shared.global [%0], [%1], 16;" :: "r"(dst), "l"(src) : "memory");
}
#define MBAR_INIT(a, c) \
    asm volatile("mbarrier.init.shared.b64 [%0], %1;" :: "r"(a), "r"((uint32_t)(c)) : "memory")
#define MBAR_ARRIVE(a) \
    asm volatile("mbarrier.arrive.shared.b64 _, [%0];" :: "r"(a) : "memory")
#define CP_MBAR_ARRIVE(a) \
    asm volatile("cp.async.mbarrier.arrive.noinc.shared.b64 [%0];" :: "r"(a) : "memory")
#define MBAR_WAIT(a, ph) do { \
    uint32_t _m = (a); uint32_t _p = (uint32_t)(ph); uint32_t _d; \
    asm volatile("{\n\t.reg .pred p;\n\tmbarrier.try_wait.parity.acquire.cta.shared::cta.b64 p, [%1], %2;\n\tselp.b32 %0, 1, 0, p;\n\t}" \
        : "=r"(_d) : "r"(_m), "r"(_p) : "memory"); \
    if (!_d) { \
        asm volatile("{\n\t.reg .pred P1;\n\tWL_%=:\n\tmbarrier.try_wait.parity.acquire.cta.shared::cta.b64 P1, [%0], %1, 0x989680;\n\t@P1 bra.uni WD_%=;\n\tbra.uni WL_%=;\n\tWD_%=:\n\t}" \
            :: "r"(_m), "r"(_p) : "memory"); \
    } \
} while (0)

__device__ __forceinline__ void ldm4(uint32_t (&r)[4], uint32_t addr) {
    asm volatile("ldmatrix.sync.aligned.m8n8.x4.shared.b16 {%0,%1,%2,%3}, [%4];"
        : "=r"(r[0]), "=r"(r[1]), "=r"(r[2]), "=r"(r[3]) : "r"(addr));
}
__device__ __forceinline__ void mma16816(float (&d)[4], const uint32_t (&a)[4],
                                         uint32_t b0, uint32_t b1) {
    asm volatile(
        "mma.sync.aligned.m16n8k16.row.col.f32.f16.f16.f32 "
        "{%0,%1,%2,%3},{%4,%5,%6,%7},{%8,%9},{%0,%1,%2,%3};"
        : "+f"(d[0]), "+f"(d[1]), "+f"(d[2]), "+f"(d[3])
        : "r"(a[0]), "r"(a[1]), "r"(a[2]), "r"(a[3]), "r"(b0), "r"(b1));
}
__device__ __forceinline__ uint32_t packh2(float2 f) {
    uint32_t u;
    asm("cvt.rn.f16x2.f32 %0, %2, %1;" : "=r"(u) : "f"(f.x), "f"(f.y));
    return u;
}

// ---------------- kernel: merged classify + pack ----------------
__global__ void prep_kernel(const int* __restrict__ ids32,
                            const float* __restrict__ vW1, const float* __restrict__ pW1,
                            float* __restrict__ out, int mask_mode) {
    if (blockIdx.x >= 256) {
        int pblk = blockIdx.x - 256;
        int head = pblk >> 7;
        const float* W = head ? pW1 : vW1;
        int q  = (pblk & 127) * 256 + threadIdx.x;
        int n  = q >> 7;
        int kq = (q & 127) * 4;
        float4 f = *(const float4*)(W + (size_t)n * DIN + kq);
        uint2 hv;
        hv.x = packh2(make_float2(f.x, f.y));
        hv.y = packh2(make_float2(f.z, f.w));
        int chunk = kq >> 5;
        int kk = kq & 31;
        unsigned char* basep = g_wpack + (size_t)head * (NCHUNK * 16384) + (size_t)chunk * 16384;
        *(uint2*)(basep + (size_t)n * 64 + kk * 2) = hv;
        return;
    }

    __shared__ int sIs64;
    if (threadIdx.x < 32) {
        int v = ids32[2 * threadIdx.x + 1] | ids32[2 * threadIdx.x + 65] |
                ids32[2 * threadIdx.x + 129] | ids32[2 * threadIdx.x + 193];
        unsigned nz = __ballot_sync(0xffffffffu, v != 0);
        if (threadIdx.x == 0) sIs64 = (nz == 0);
    }
    __syncthreads();
    int t = blockIdx.x * blockDim.x + threadIdx.x;
    int type = sIs64 ? ids32[2 * t] : ids32[t];
    bool vm = (type == 1);
    bool pm = (type == 2);

    float* row = out + (size_t)t * 6;
    #pragma unroll
    for (int o = 0; o < 6; o++) row[o] = 0.0f;

    if (mask_mode == 1) {
        out[TOKENS * 6 + t]          = vm ? 1.0f : 0.0f;
        out[TOKENS * 6 + TOKENS + t] = pm ? 1.0f : 0.0f;
    } else if (mask_mode == 2) {
        unsigned char* m = (unsigned char*)(out + TOKENS * 6);
        m[t]          = vm ? 1 : 0;
        m[TOKENS + t] = pm ? 1 : 0;
    }

    int lane = threadIdx.x & 31;
    unsigned vb = __ballot_sync(0xffffffffu, vm);
    if (vm) {
        int leader = __ffs(vb) - 1;
        int base = 0;
        if (lane == leader) base = atomicAdd(&g_cnt[0], __popc(vb));
        base = __shfl_sync(vb, base, leader);
        g_vidx[base + __popc(vb & ((1u << lane) - 1u))] = t;
    }
    unsigned pb = __ballot_sync(0xffffffffu, pm);
    if (pm) {
        int leader = __ffs(pb) - 1;
        int base = 0;
        if (lane == leader) base = atomicAdd(&g_cnt[1], __popc(pb));
        base = __shfl_sync(pb, base, leader);
        g_pidx[base + __popc(pb & ((1u << lane) - 1u))] = t;
    }
}

// ---------------- kernel: warp-specialized persistent fp16 HMMA MLP ----------------
__global__ __launch_bounds__(NT, 1)
void mlp_kernel(const float* __restrict__ repr3,
                const float* __restrict__ vW2, const float* __restrict__ vB1, const float* __restrict__ vB2,
                const float* __restrict__ pW2, const float* __restrict__ pB1, const float* __restrict__ pB2,
                float* __restrict__ out)
{
    extern __shared__ unsigned char smem[];
    const uint32_t sb = smem_u32(smem);
    const int tid  = threadIdx.x;
    const int wid  = tid >> 5;
    const int lane = tid & 31;
    const bool isProd = (tid >= 256);
    const int ptid = tid - 256;        // producer thread id 0..127

    int*   sTok  = (int*)(smem + TOK_OFF);
    float* sW2   = (float*)(smem + W2_OFF);
    float* sB1   = (float*)(smem + B1_OFF);
    float* sB2   = (float*)(smem + B2_OFF);
    float* sRed  = (float*)(smem + RED_OFF);
    int*   sTile = (int*)(smem + TILE_OFF);

    // mbarriers: full[s] = MBAR+ s*16, empty[s] = +8
    if (tid == 0) {
        #pragma unroll
        for (int s = 0; s < NSTAGE; s++) {
            MBAR_INIT(sb + MBAR_OFF + s * 16, 2 * NPROD);   // full: 128 cp-arrive + 128 STS-arrive
            MBAR_INIT(sb + MBAR_OFF + s * 16 + 8, 8);       // empty: 8 consumer warps
        }
        *sTile = atomicAdd(&g_cnt[2], 1);
    }
    __syncthreads();
    int tile = *sTile;

    const int nv = g_cnt[0], np = g_cnt[1];
    const int nvt = (nv + BM - 1) / BM;
    const int npt = (np + BM - 1) / BM;
    const int ntiles = nvt + npt;

    // consumer geometry (as R7)
    const int wm = wid & 1;
    const int wn = wid >> 1;
    const int m0 = wm * 32;
    const int n0 = wn * 64;
    const uint32_t aLdOff = (uint32_t)(((lane >> 3) & 1) * 8 + (lane & 7)) * ROWB + (uint32_t)(lane >> 4) * 16;
    const uint32_t bLdOff = (uint32_t)(((lane >> 4) & 1) * 8 + (lane & 7)) * ROWB + (uint32_t)((lane >> 3) & 1) * 16;

    // persistent ring cursors
    int pst = 0, pph = 1;     // producer: first empty-wait passes
    int cst = 0, cph = 0;     // consumer

    int prevHead = -1;

    while (tile < ntiles) {
        const int head  = (tile >= nvt);
        const int tIdx  = head ? (tile - nvt) : tile;
        const int count = head ? np : nv;
        const int base  = tIdx * BM;
        const int* list  = head ? g_pidx : g_vidx;
        const int odim   = head ? 2 : 6;
        const unsigned char* wsrc = g_wpack + (size_t)head * (NCHUNK * 16384);

        // ---- tile prologue (all threads) ----
        if (tid < BM) {
            int m = base + tid;
            sTok[tid] = (m < count) ? list[m] : list[0];
        }
        if (head != prevHead) {
            const float* W2p = head ? pW2 : vW2;
            const float* B1p = head ? pB1 : vB1;
            const float* B2p = head ? pB2 : vB2;
            for (int i = tid; i < 6 * HDIM; i += NT) sW2[i] = (i < odim * HDIM) ? W2p[i] : 0.0f;
            if (tid < HDIM) sB1[tid] = B1p[tid];
            if (tid < odim) sB2[tid] = B2p[tid];
        }
        prevHead = head;
        __syncthreads();

        if (isProd) {
            // ---- producer: 4 token-row pointers + B offsets ----
            const int ar = ptid >> 3;          // base row 0..15
            const int ac = ptid & 7;           // float4 col 0..7
            const float* ap0 = repr3 + (size_t)sTok[ar]      * DIN + ac * 4;
            const float* ap1 = repr3 + (size_t)sTok[ar + 16] * DIN + ac * 4;
            const float* ap2 = repr3 + (size_t)sTok[ar + 32] * DIN + ac * 4;
            const float* ap3 = repr3 + (size_t)sTok[ar + 48] * DIN + ac * 4;

            for (int ch = 0; ch < NCHUNK; ch++) {
                const uint32_t fullb  = sb + MBAR_OFF + pst * 16;
                const uint32_t emptyb = fullb + 8;
                MBAR_WAIT(emptyb, pph);

                // B: 8 cp.asyncs
                const unsigned char* csrc = wsrc + (size_t)ch * 16384;
                const uint32_t bDst = sb + B_OFF + pst * B_ST;
                #pragma unroll
                for (int i = 0; i < 8; i++) {
                    int idx = ptid + i * NPROD;        // 0..1023
                    int row = idx >> 2;
                    int c16 = idx & 3;
                    cp_async16(bDst + (uint32_t)row * ROWB + c16 * 16,
                               csrc + (size_t)row * 64 + c16 * 16);
                }
                // A: 4 LDG.128 -> cvt -> STS
                const int ko = ch * KC;
                float4 f0 = *(const float4*)(ap0 + ko);
                float4 f1 = *(const float4*)(ap1 + ko);
                float4 f2 = *(const float4*)(ap2 + ko);
                float4 f3 = *(const float4*)(ap3 + ko);
                unsigned char* aDst = smem + A16_OFF + pst * A16_ST + ac * 8;
                *(uint2*)(aDst + (uint32_t)(ar)      * ROWB) = make_uint2(packh2(make_float2(f0.x, f0.y)), packh2(make_float2(f0.z, f0.w)));
                *(uint2*)(aDst + (uint32_t)(ar + 16) * ROWB) = make_uint2(packh2(make_float2(f1.x, f1.y)), packh2(make_float2(f1.z, f1.w)));
                *(uint2*)(aDst + (uint32_t)(ar + 32) * ROWB) = make_uint2(packh2(make_float2(f2.x, f2.y)), packh2(make_float2(f2.z, f2.w)));
                *(uint2*)(aDst + (uint32_t)(ar + 48) * ROWB) = make_uint2(packh2(make_float2(f3.x, f3.y)), packh2(make_float2(f3.z, f3.w)));

                CP_MBAR_ARRIVE(fullb);     // arrives when this thread's B cps land
                MBAR_ARRIVE(fullb);        // releases the A STS
                pst = (pst + 1) & (NSTAGE - 1);
                if (pst == 0) pph ^= 1;
            }
            __syncthreads();   // meet consumers after their epilogue stores
        } else {
            // ---- consumer: MMA mainloop ----
            float c[2][8][4];
            #pragma unroll
            for (int mi = 0; mi < 2; mi++)
                #pragma unroll
                for (int ni = 0; ni < 8; ni++)
                    #pragma unroll
                    for (int j = 0; j < 4; j++) c[mi][ni][j] = 0.0f;

            for (int ch = 0; ch < NCHUNK; ch++) {
                const uint32_t fullb  = sb + MBAR_OFF + cst * 16;
                const uint32_t emptyb = fullb + 8;
                MBAR_WAIT(fullb, cph);

                const uint32_t aB = sb + A16_OFF + cst * A16_ST;
                const uint32_t bB = sb + B_OFF + cst * B_ST;
                #pragma unroll
                for (int ks = 0; ks < 2; ks++) {
                    uint32_t ah[2][4];
                    #pragma unroll
                    for (int mi = 0; mi < 2; mi++) {
                        uint32_t off = (uint32_t)(m0 + mi * 16) * ROWB + (uint32_t)ks * 32 + aLdOff;
                        ldm4(ah[mi], aB + off);
                    }
                    #pragma unroll
                    for (int npp = 0; npp < 4; npp++) {
                        uint32_t off = (uint32_t)(n0 + npp * 16) * ROWB + (uint32_t)ks * 32 + bLdOff;
                        uint32_t b[4];
                        ldm4(b, bB + off);
                        mma16816(c[0][2 * npp],     ah[0], b[0], b[1]);
                        mma16816(c[0][2 * npp + 1], ah[0], b[2], b[3]);
                        mma16816(c[1][2 * npp],     ah[1], b[0], b[1]);
                        mma16816(c[1][2 * npp + 1], ah[1], b[2], b[3]);
                    }
                }
                __syncwarp();
                if (lane == 0) MBAR_ARRIVE(emptyb);
                cst = (cst + 1) & (NSTAGE - 1);
                if (cst == 0) cph ^= 1;
            }

            // ---- epilogue: bias + exact GELU + 256->{6,2} layer ----
            #pragma unroll
            for (int mi = 0; mi < 2; mi++) {
                #pragma unroll
                for (int half = 0; half < 2; half++) {
                    float a6[6] = {0.f, 0.f, 0.f, 0.f, 0.f, 0.f};
                    #pragma unroll
                    for (int ni = 0; ni < 8; ni++) {
                        #pragma unroll
                        for (int e = 0; e < 2; e++) {
                            int col = n0 + ni * 8 + (lane & 3) * 2 + e;
                            float x = c[mi][ni][half * 2 + e] + sB1[col];
                            float hgl = 0.5f * x * (1.0f + erff(x * 0.70710678118654752f));
                            a6[0] = fmaf(hgl, sW2[0 * HDIM + col], a6[0]);
                            a6[1] = fmaf(hgl, sW2[1 * HDIM + col], a6[1]);
                            if (odim == 6) {
                                a6[2] = fmaf(hgl, sW2[2 * HDIM + col], a6[2]);
                                a6[3] = fmaf(hgl, sW2[3 * HDIM + col], a6[3]);
                                a6[4] = fmaf(hgl, sW2[4 * HDIM + col], a6[4]);
                                a6[5] = fmaf(hgl, sW2[5 * HDIM + col], a6[5]);
                            }
                        }
                    }
                    #pragma unroll
                    for (int o = 0; o < 6; o++) {
                        a6[o] += __shfl_xor_sync(0xffffffffu, a6[o], 1);
                        a6[o] += __shfl_xor_sync(0xffffffffu, a6[o], 2);
                    }
                    if ((lane & 3) == 0) {
                        int row = m0 + mi * 16 + half * 8 + (lane >> 2);
                        #pragma unroll
                        for (int o = 0; o < 6; o++)
                            sRed[(wn * BM + row) * 6 + o] = a6[o];
                    }
                }
            }
            __syncthreads();   // meet producers; sRed visible
        }

        // ---- output + next ticket (all threads at same barrier count) ----
        if (tid < BM && base + tid < count) {
            float* orow = out + (size_t)sTok[tid] * 6;
            #pragma unroll
            for (int o = 0; o < 6; o++) {
                if (o < odim) {
                    float v = sRed[(0 * BM + tid) * 6 + o] + sRed[(1 * BM + tid) * 6 + o]
                            + sRed[(2 * BM + tid) * 6 + o] + sRed[(3 * BM + tid) * 6 + o]
                            + sB2[o];
                    orow[o] = v;
                }
            }
        }
        if (tid == 0) *sTile = atomicAdd(&g_cnt[2], 1);
        __syncthreads();
        tile = *sTile;
    }
}

// ---------------- launch ----------------
extern "C" void kernel_launch(void* const* d_in, const int* in_sizes, int n_in,
                              void* d_out, int out_size) {
    const float* repr3 = (const float*)d_in[0];
    const int*   ids   = (const int*)d_in[1];
    const float* vW1 = (const float*)d_in[2];
    const float* vb1 = (const float*)d_in[3];
    const float* vW2 = (const float*)d_in[4];
    const float* vb2 = (const float*)d_in[5];
    const float* pW1 = (const float*)d_in[6];
    const float* pb1 = (const float*)d_in[7];
    const float* pW2 = (const float*)d_in[8];
    const float* pb2 = (const float*)d_in[9];
    float* out = (float*)d_out;

    int mask_mode = 0;
    if (out_size >= TOKENS * 6 + 2 * TOKENS)      mask_mode = 1;
    else if (out_size >= TOKENS * 6 + TOKENS / 2) mask_mode = 2;

    cudaFuncSetAttribute(mlp_kernel, cudaFuncAttributeMaxDynamicSharedMemorySize, SMEM_TOTAL);

    void* cntAddr = nullptr;
    cudaGetSymbolAddress(&cntAddr, g_cnt);
    cudaMemsetAsync(cntAddr, 0, 3 * sizeof(int));

    prep_kernel<<<512, 256>>>(ids, vW1, pW1, out, mask_mode);
    mlp_kernel<<<GRID, NT, SMEM_TOTAL>>>(repr3, vW2, vb1, vb2, pW2, pb1, pb2, out);
}